// round 1
// baseline (speedup 1.0000x reference)
#include <cuda_runtime.h>
#include <cstdint>

// ============================================================================
// OneHotEncoding: brute-force nearest-point search (128 receivers x 1e6 pts)
// + one-hot / concat output assembly.
//
// Output layout (float32), matching reference tuple flattened:
//   [0, 4L)            input_tensor: per point (x, y, z, one_hot)
//   [4L, 4L+3B)        closest_points [B,3]
//   [4L+3B, 4L+4B)     min_index as float [B]
// ============================================================================

#define TILE    512     // points staged per tile
#define THREADS 512     // threads per block (16 warps)
#define RPW     8       // receivers per warp (16 warps * 8 = 128)
#define GRID    152     // one block per SM on GB300

__device__ unsigned long long g_best[128];

// ---- Blackwell packed f32x2 helpers (2 fp32 ops per fma-pipe issue) ----
#define ADD2(out,a,b)   asm("add.rn.f32x2 %0, %1, %2;"     : "=l"(out) : "l"(a), "l"(b))
#define MUL2(out,a,b)   asm("mul.rn.f32x2 %0, %1, %2;"     : "=l"(out) : "l"(a), "l"(b))
#define FMA2(out,a,b,c) asm("fma.rn.f32x2 %0, %1, %2, %3;" : "=l"(out) : "l"(a), "l"(b), "l"(c))
#define PACK2(out,lo,hi)  asm("mov.b64 %0, {%1, %2};" : "=l"(out) : "r"(lo), "r"(hi))
#define UNPACK2(lo,hi,in) asm("mov.b64 {%0, %1}, %2;" : "=r"(lo), "=r"(hi) : "l"(in))

// ---------------------------------------------------------------------------
__global__ void init_best_kernel(int B) {
    int t = threadIdx.x;
    if (t < B) g_best[t] = 0xFFFFFFFFFFFFFFFFull;
}

// ---------------------------------------------------------------------------
__global__ void __launch_bounds__(THREADS, 1)
nn_kernel(const float* __restrict__ pts,   // [L,3]
          const float* __restrict__ recv,  // [B,3]
          float* __restrict__ out,         // [4L + 4B]
          int L, int B, int nTiles)
{
    __shared__ __align__(16) float s_p[3][TILE];

    const int tid   = threadIdx.x;
    const int lane  = tid & 31;
    const int wid   = tid >> 5;
    const int rbase = wid * RPW;
    const bool ract = (rbase < B);   // receiver group active (always true for B=128)

    // Load this warp's 8 receivers, negate, splat into f32x2 pairs (loop-invariant regs)
    unsigned long long nrx[RPW], nry[RPW], nrz[RPW];
#pragma unroll
    for (int r = 0; r < RPW; ++r) {
        int rb = rbase + r;
        float x = 0.f, y = 0.f, z = 0.f;
        if (ract && rb < B) {
            x = -recv[3 * rb + 0];
            y = -recv[3 * rb + 1];
            z = -recv[3 * rb + 2];
        }
        unsigned int xu = __float_as_uint(x);
        unsigned int yu = __float_as_uint(y);
        unsigned int zu = __float_as_uint(z);
        PACK2(nrx[r], xu, xu);
        PACK2(nry[r], yu, yu);
        PACK2(nrz[r], zu, zu);
    }

    float        best[RPW];
    unsigned int bidx[RPW];
#pragma unroll
    for (int r = 0; r < RPW; ++r) { best[r] = 3.4e38f; bidx[r] = 0u; }

    const int L3 = L * 3;

    for (int tile = blockIdx.x; tile < nTiles; tile += gridDim.x) {
        const int base = tile * TILE;   // global point index base of this tile

        __syncthreads();   // previous tile's compute done before overwriting smem

        // ---- stage TILE points (TILE*3 floats) AoS->SoA into smem ----
#pragma unroll
        for (int j = 0; j < (TILE * 3) / THREADS; ++j) {
            int e  = tid + j * THREADS;      // float index within tile [0, 3*TILE)
            int ge = base * 3 + e;           // global float index
            float v = (ge < L3) ? pts[ge] : 1.0e30f;   // pad -> huge dist, never wins
            int p = e / 3;
            int c = e - p * 3;
            s_p[c][p] = v;
        }
        __syncthreads();

        // ---- write output pts part: out[4*gp + {0,1,2,3}] = (x,y,z,0) ----
        {
            int gp = base + tid;             // TILE == THREADS: one point per thread
            if (gp < L) {
                float4 o = make_float4(s_p[0][tid], s_p[1][tid], s_p[2][tid], 0.0f);
                *reinterpret_cast<float4*>(out + 4 * gp) = o;
            }
        }

        // ---- compute: each lane handles 2 points/iter vs this warp's 8 receivers ----
        unsigned int ia0 = (unsigned int)(base + 2 * lane);
#pragma unroll 2
        for (int k = 0; k < TILE / 64; ++k) {
            int loc = 2 * lane + 64 * k;
            float2 fx = *reinterpret_cast<const float2*>(&s_p[0][loc]);
            float2 fy = *reinterpret_cast<const float2*>(&s_p[1][loc]);
            float2 fz = *reinterpret_cast<const float2*>(&s_p[2][loc]);
            unsigned long long Px, Py, Pz;
            PACK2(Px, __float_as_uint(fx.x), __float_as_uint(fx.y));
            PACK2(Py, __float_as_uint(fy.x), __float_as_uint(fy.y));
            PACK2(Pz, __float_as_uint(fz.x), __float_as_uint(fz.y));
            unsigned int ia = ia0 + (unsigned int)(64 * k);

#pragma unroll
            for (int r = 0; r < RPW; ++r) {
                unsigned long long dx, dy, dz, s;
                ADD2(dx, Px, nrx[r]);            // p - recv  (exact sub)
                ADD2(dy, Py, nry[r]);
                ADD2(dz, Pz, nrz[r]);
                MUL2(s, dx, dx);                 // d2 = dx^2 + dy^2 + dz^2
                FMA2(s, dy, dy, s);
                FMA2(s, dz, dz, s);
                unsigned int ua, ub;
                UNPACK2(ua, ub, s);
                float da = __uint_as_float(ua);
                float db = __uint_as_float(ub);
                // strict < keeps the FIRST (lowest-index) minimum, matching argmin
                if (da < best[r]) { best[r] = da; bidx[r] = ia; }
                if (db < best[r]) { best[r] = db; bidx[r] = ia + 1u; }
            }
        }
    }

    // ---- per-warp reduce + global merge (packed u64: d2bits<<32 | idx) ----
#pragma unroll
    for (int r = 0; r < RPW; ++r) {
        unsigned long long pb =
            (((unsigned long long)__float_as_uint(best[r])) << 32) |
            (unsigned long long)bidx[r];
#pragma unroll
        for (int m = 16; m > 0; m >>= 1) {
            unsigned long long o = __shfl_xor_sync(0xffffffffu, pb, m);
            pb = (o < pb) ? o : pb;
        }
        if (lane == 0 && ract && (rbase + r) < B) {
            atomicMin(&g_best[rbase + r], pb);
        }
    }
}

// ---------------------------------------------------------------------------
__global__ void finalize_kernel(const float* __restrict__ pts,
                                float* __restrict__ out, int L, int B)
{
    int t = threadIdx.x;
    if (t < B) {
        unsigned long long b = g_best[t];
        unsigned int idx = (unsigned int)(b & 0xFFFFFFFFull);
        // closest_points [B,3]
        float* cp = out + 4 * L;
        cp[3 * t + 0] = pts[3 * idx + 0];
        cp[3 * t + 1] = pts[3 * idx + 1];
        cp[3 * t + 2] = pts[3 * idx + 2];
        // min_index as float [B]
        out[4 * L + 3 * B + t] = (float)idx;
        // scatter one-hot into interleaved output column 3
        out[4 * (size_t)idx + 3] = 1.0f;
    }
    // reference quirk: for B > 1, index 0 is also set to 1
    if (t == 0 && B > 1) out[3] = 1.0f;
}

// ---------------------------------------------------------------------------
extern "C" void kernel_launch(void* const* d_in, const int* in_sizes, int n_in,
                              void* d_out, int out_size)
{
    const float* pts  = (const float*)d_in[0];   // mesh_3D flattened [L,3]
    const float* recv = (const float*)d_in[1];   // receiver_pos [B,3]
    float* out = (float*)d_out;

    int L = in_sizes[0] / 3;
    int B = in_sizes[1] / 3;   // 128
    int nTiles = (L + TILE - 1) / TILE;

    init_best_kernel<<<1, 128>>>(B);
    nn_kernel<<<GRID, THREADS>>>(pts, recv, out, L, B, nTiles);
    finalize_kernel<<<1, 128>>>(pts, out, L, B);
}

// round 2
// speedup vs baseline: 1.1383x; 1.1383x over previous
#include <cuda_runtime.h>
#include <cstdint>

// ============================================================================
// OneHotEncoding: brute-force nearest-point search (128 receivers x 1e6 pts)
// + one-hot / concat output assembly.
//
// Output layout (float32):
//   [0, 4L)            input_tensor: per point (x, y, z, one_hot)
//   [4L, 4L+3B)        closest_points [B,3]
//   [4L+3B, 4L+4B)     min_index as float [B]
// ============================================================================

#define TILE    512     // points staged per tile
#define THREADS 512     // threads per block (16 warps)
#define RPW     8       // receivers per warp (16 warps * 8 = 128)
#define GRID    152     // one block per SM on GB300

__device__ unsigned long long g_best[128];

// ---- Blackwell packed f32x2 helpers (2 fp32 ops per fma-pipe issue) ----
#define ADD2(out,a,b)   asm("add.rn.f32x2 %0, %1, %2;"     : "=l"(out) : "l"(a), "l"(b))
#define MUL2(out,a,b)   asm("mul.rn.f32x2 %0, %1, %2;"     : "=l"(out) : "l"(a), "l"(b))
#define FMA2(out,a,b,c) asm("fma.rn.f32x2 %0, %1, %2, %3;" : "=l"(out) : "l"(a), "l"(b), "l"(c))
#define PACK2(out,lo,hi)  asm("mov.b64 %0, {%1, %2};" : "=l"(out) : "r"(lo), "r"(hi))
#define UNPACK2(lo,hi,in) asm("mov.b64 {%0, %1}, %2;" : "=r"(lo), "=r"(hi) : "l"(in))

// ---------------------------------------------------------------------------
__global__ void init_best_kernel(int B) {
    int t = threadIdx.x;
    if (t < B) g_best[t] = 0xFFFFFFFFFFFFFFFFull;
}

// ---------------------------------------------------------------------------
__global__ void __launch_bounds__(THREADS, 1)
nn_kernel(const float* __restrict__ pts,   // [L,3]
          const float* __restrict__ recv,  // [B,3]
          float* __restrict__ out,         // [4L + 4B]
          int L, int B, int nTiles)
{
    // double-buffered SoA tile: [buf][coord][point]
    __shared__ __align__(16) float s_p[2][3][TILE];

    const int tid   = threadIdx.x;
    const int lane  = tid & 31;
    const int wid   = tid >> 5;
    const int rbase = wid * RPW;

    // Load this warp's 8 receivers, negate, splat into f32x2 pairs
    unsigned long long nrx[RPW], nry[RPW], nrz[RPW];
#pragma unroll
    for (int r = 0; r < RPW; ++r) {
        int rb = rbase + r;
        float x = 0.f, y = 0.f, z = 0.f;
        if (rb < B) {
            x = -recv[3 * rb + 0];
            y = -recv[3 * rb + 1];
            z = -recv[3 * rb + 2];
        }
        unsigned int xu = __float_as_uint(x);
        unsigned int yu = __float_as_uint(y);
        unsigned int zu = __float_as_uint(z);
        PACK2(nrx[r], xu, xu);
        PACK2(nry[r], yu, yu);
        PACK2(nrz[r], zu, zu);
    }

    float        best[RPW];
    unsigned int bidx[RPW];
#pragma unroll
    for (int r = 0; r < RPW; ++r) { best[r] = 3.4e38f; bidx[r] = 0u; }

    const int L3 = L * 3;

    // ---- prologue: stage first tile into buffer 0 ----
    {
        int base3 = blockIdx.x * (TILE * 3);
#pragma unroll
        for (int j = 0; j < 3; ++j) {
            int e  = tid + j * THREADS;
            int ge = base3 + e;
            float v = (ge < L3) ? pts[ge] : 1.0e30f;
            int p = e / 3;
            int c = e - p * 3;
            s_p[0][c][p] = v;
        }
    }
    __syncthreads();

    int buf = 0;
    for (int tile = blockIdx.x; tile < nTiles; tile += GRID) {
        const int base = tile * TILE;
        const int nxt  = tile + GRID;

        // ---- prefetch next tile into registers (latency overlapped) ----
        float pf[3];
        if (nxt < nTiles) {
            int base3 = nxt * (TILE * 3);
#pragma unroll
            for (int j = 0; j < 3; ++j) {
                int ge = base3 + tid + j * THREADS;
                pf[j] = (ge < L3) ? pts[ge] : 1.0e30f;
            }
        }

        // ---- write output pts: out[4*gp + {0,1,2,3}] = (x,y,z,0) ----
        {
            int gp = base + tid;             // TILE == THREADS
            if (gp < L) {
                float4 o = make_float4(s_p[buf][0][tid], s_p[buf][1][tid],
                                       s_p[buf][2][tid], 0.0f);
                *reinterpret_cast<float4*>(out + 4 * gp) = o;
            }
        }

        // ---- compute: 4 points/lane/iter vs this warp's 8 receivers ----
#pragma unroll 2
        for (int k = 0; k < TILE / 128; ++k) {
            int loc = 4 * lane + 128 * k;
            float4 fx = *reinterpret_cast<const float4*>(&s_p[buf][0][loc]);
            float4 fy = *reinterpret_cast<const float4*>(&s_p[buf][1][loc]);
            float4 fz = *reinterpret_cast<const float4*>(&s_p[buf][2][loc]);
            unsigned long long Px01, Px23, Py01, Py23, Pz01, Pz23;
            PACK2(Px01, __float_as_uint(fx.x), __float_as_uint(fx.y));
            PACK2(Px23, __float_as_uint(fx.z), __float_as_uint(fx.w));
            PACK2(Py01, __float_as_uint(fy.x), __float_as_uint(fy.y));
            PACK2(Py23, __float_as_uint(fy.z), __float_as_uint(fy.w));
            PACK2(Pz01, __float_as_uint(fz.x), __float_as_uint(fz.y));
            PACK2(Pz23, __float_as_uint(fz.z), __float_as_uint(fz.w));
            const unsigned int ia = (unsigned int)(base + loc);

#pragma unroll
            for (int r = 0; r < RPW; ++r) {
                unsigned long long dx0, dy0, dz0, s0;
                unsigned long long dx1, dy1, dz1, s1;
                ADD2(dx0, Px01, nrx[r]);            // p - recv (exact sub)
                ADD2(dy0, Py01, nry[r]);
                ADD2(dz0, Pz01, nrz[r]);
                ADD2(dx1, Px23, nrx[r]);
                ADD2(dy1, Py23, nry[r]);
                ADD2(dz1, Pz23, nrz[r]);
                MUL2(s0, dx0, dx0);
                FMA2(s0, dy0, dy0, s0);
                FMA2(s0, dz0, dz0, s0);
                MUL2(s1, dx1, dx1);
                FMA2(s1, dy1, dy1, s1);
                FMA2(s1, dz1, dz1, s1);
                unsigned int u0, u1, u2, u3;
                UNPACK2(u0, u1, s0);
                UNPACK2(u2, u3, s1);
                float d0 = __uint_as_float(u0);
                float d1 = __uint_as_float(u1);
                float d2 = __uint_as_float(u2);
                float d3 = __uint_as_float(u3);
                // 4->1 min tree (FMNMX), single compare vs running best,
                // rare branch resolves which of the 4 indices won.
                float m01 = fminf(d0, d1);
                float m23 = fminf(d2, d3);
                float m   = fminf(m01, m23);
                if (m < best[r]) {               // strict <: keep first min
                    best[r] = m;
                    unsigned int id = ia + 3u;   // descending priority ->
                    if (d2 <= m) id = ia + 2u;   // smallest matching index
                    if (d1 <= m) id = ia + 1u;
                    if (d0 <= m) id = ia;
                    bidx[r] = id;
                }
            }
        }

        // ---- store prefetched tile into other buffer, single sync ----
        if (nxt < nTiles) {
#pragma unroll
            for (int j = 0; j < 3; ++j) {
                int e = tid + j * THREADS;
                int p = e / 3;
                int c = e - p * 3;
                s_p[buf ^ 1][c][p] = pf[j];
            }
        }
        buf ^= 1;
        __syncthreads();
    }

    // ---- per-warp reduce + global merge (packed u64: d2bits<<32 | idx) ----
#pragma unroll
    for (int r = 0; r < RPW; ++r) {
        unsigned long long pb =
            (((unsigned long long)__float_as_uint(best[r])) << 32) |
            (unsigned long long)bidx[r];
#pragma unroll
        for (int m = 16; m > 0; m >>= 1) {
            unsigned long long o = __shfl_xor_sync(0xffffffffu, pb, m);
            pb = (o < pb) ? o : pb;
        }
        if (lane == 0 && (rbase + r) < B) {
            atomicMin(&g_best[rbase + r], pb);
        }
    }
}

// ---------------------------------------------------------------------------
__global__ void finalize_kernel(const float* __restrict__ pts,
                                float* __restrict__ out, int L, int B)
{
    int t = threadIdx.x;
    if (t < B) {
        unsigned long long b = g_best[t];
        unsigned int idx = (unsigned int)(b & 0xFFFFFFFFull);
        float* cp = out + 4 * L;
        cp[3 * t + 0] = pts[3 * idx + 0];
        cp[3 * t + 1] = pts[3 * idx + 1];
        cp[3 * t + 2] = pts[3 * idx + 2];
        out[4 * L + 3 * B + t] = (float)idx;
        out[4 * (size_t)idx + 3] = 1.0f;
    }
    if (t == 0 && B > 1) out[3] = 1.0f;   // reference quirk: index 0 also set
}

// ---------------------------------------------------------------------------
extern "C" void kernel_launch(void* const* d_in, const int* in_sizes, int n_in,
                              void* d_out, int out_size)
{
    const float* pts  = (const float*)d_in[0];   // mesh_3D flattened [L,3]
    const float* recv = (const float*)d_in[1];   // receiver_pos [B,3]
    float* out = (float*)d_out;

    int L = in_sizes[0] / 3;
    int B = in_sizes[1] / 3;   // 128
    int nTiles = (L + TILE - 1) / TILE;

    init_best_kernel<<<1, 128>>>(B);
    nn_kernel<<<GRID, THREADS>>>(pts, recv, out, L, B, nTiles);
    finalize_kernel<<<1, 128>>>(pts, out, L, B);
}